// round 3
// baseline (speedup 1.0000x reference)
#include <cuda_runtime.h>
#include <cuda_bf16.h>
#include <math.h>

#define IN_F   256
#define OUT_F  256
#define N_E    10000
#define N_KC   2000
#define ALPHA  0.2f

// ---------------- scratch (static __device__, no allocation) ----------------
__device__ float g_kcWh[N_KC * OUT_F];     // 2 MB
__device__ float g_exEh[N_E * OUT_F];      // 10 MB
__device__ float g_feat[N_E * 2 * OUT_F];  // 20 MB
__device__ float g_e1[N_E];
__device__ float g_e2[N_KC];
__device__ float g_v1[IN_F];
__device__ float g_v2[IN_F];
__device__ float g_rdT[2 * OUT_F * OUT_F]; // rd_w transposed: [512][256]

// ---------------- prep: v1 = W1@a1, v2 = W1@a2, rdT = rd_w^T ----------------
__global__ void prep_kernel(const float* __restrict__ W1, const float* __restrict__ a,
                            const float* __restrict__ rd_w)
{
    int b = blockIdx.x;
    if (b == 0) {
        int k = threadIdx.x; // 0..255
        float s1 = 0.f, s2 = 0.f;
        #pragma unroll 8
        for (int j = 0; j < OUT_F; j++) {
            float w = W1[k * OUT_F + j];
            s1 += w * a[j];
            s2 += w * a[OUT_F + j];
        }
        g_v1[k] = s1;
        g_v2[k] = s2;
    } else {
        int idx = (b - 1) * 256 + threadIdx.x;
        if (idx < 2 * OUT_F * OUT_F) {
            int k = idx >> 8;       // 0..511
            int n = idx & 255;      // 0..255
            g_rdT[idx] = rd_w[n * (2 * OUT_F) + k];
        }
    }
}

// ---------------- row dot: out[i] = dot(X[i,:256], v) ----------------
__global__ void rowdot_kernel(const float* __restrict__ X, const float* __restrict__ v,
                              float* __restrict__ out, int M)
{
    int gwarp = (blockIdx.x * blockDim.x + threadIdx.x) >> 5;
    int lane = threadIdx.x & 31;
    if (gwarp >= M) return;
    const float* row = X + (size_t)gwarp * IN_F;
    float s = 0.f;
    #pragma unroll
    for (int k = lane; k < IN_F; k += 32) s += row[k] * v[k];
    #pragma unroll
    for (int o = 16; o; o >>= 1) s += __shfl_xor_sync(0xFFFFFFFFu, s, o);
    if (lane == 0) out[gwarp] = s;
}

// ---------------- tiled SGEMM: C[M,N] = A[M,K] @ B[K,N] ----------------
// BM=128, BN=64, BK=16, per-thread 8x4. N % 64 == 0, K % 16 == 0 assumed.
// epi==1: C = elu(C + bias)
#define GBM 128
#define GBN 64
#define GBK 16
__global__ __launch_bounds__(256) void sgemm_kernel(
    const float* __restrict__ A, const float* __restrict__ B, float* __restrict__ C,
    int M, int N, int K, const float* __restrict__ bias, int epi)
{
    __shared__ float As[GBK][GBM];
    __shared__ float Bs[GBK][GBN];
    int tid = threadIdx.x;
    int bm = blockIdx.y * GBM;
    int bn = blockIdx.x * GBN;
    int tx = tid & 15;          // 0..15 -> 4 cols
    int ty = tid >> 4;          // 0..15 -> 8 rows
    float acc[8][4];
    #pragma unroll
    for (int m = 0; m < 8; m++)
        #pragma unroll
        for (int n = 0; n < 4; n++) acc[m][n] = 0.f;

    int brow = tid >> 4;          // 0..15
    int bcol = (tid & 15) * 4;    // 0..60

    for (int k0 = 0; k0 < K; k0 += GBK) {
        // load A tile 128x16 (2 float4 per thread)
        #pragma unroll
        for (int l = 0; l < 2; l++) {
            int f = tid + l * 256;        // 0..511 float4 id
            int row = f >> 2;             // 0..127
            int col = (f & 3) * 4;        // 0,4,8,12
            float4 av;
            if (bm + row < M)
                av = *(const float4*)&A[(size_t)(bm + row) * K + k0 + col];
            else
                av = make_float4(0.f, 0.f, 0.f, 0.f);
            As[col + 0][row] = av.x;
            As[col + 1][row] = av.y;
            As[col + 2][row] = av.z;
            As[col + 3][row] = av.w;
        }
        // load B tile 16x64 (1 float4 per thread)
        *(float4*)&Bs[brow][bcol] = *(const float4*)&B[(size_t)(k0 + brow) * N + bn + bcol];
        __syncthreads();
        #pragma unroll
        for (int k = 0; k < GBK; k++) {
            float4 a0 = *(const float4*)&As[k][ty * 8];
            float4 a1 = *(const float4*)&As[k][ty * 8 + 4];
            float4 b0 = *(const float4*)&Bs[k][tx * 4];
            float ar[8] = {a0.x, a0.y, a0.z, a0.w, a1.x, a1.y, a1.z, a1.w};
            float br[4] = {b0.x, b0.y, b0.z, b0.w};
            #pragma unroll
            for (int m = 0; m < 8; m++)
                #pragma unroll
                for (int n = 0; n < 4; n++)
                    acc[m][n] = fmaf(ar[m], br[n], acc[m][n]);
        }
        __syncthreads();
    }
    #pragma unroll
    for (int m = 0; m < 8; m++) {
        int row = bm + ty * 8 + m;
        if (row >= M) continue;
        #pragma unroll
        for (int n = 0; n < 4; n++) {
            int col = bn + tx * 4 + n;
            float v = acc[m][n];
            if (epi == 1) {
                v += bias[col];
                v = v > 0.f ? v : expm1f(v);
            }
            C[(size_t)row * N + col] = v;
        }
    }
}

// ---------------- fused masked-softmax attention + aggregation ----------------
// 8 exercise rows per block, 256 threads. Writes new_kc and new_kc*exEh into feat.
#define ROWS 8
#define NCH  8   // ceil(2000/256)
__global__ __launch_bounds__(256) void attn_kernel(
    const float* __restrict__ e1, const float* __restrict__ e2,
    const int* __restrict__ adj, const float* __restrict__ kcWh,
    const float* __restrict__ exEh, float* __restrict__ feat)
{
    __shared__ float e2s[N_KC];
    __shared__ unsigned maskb[ROWS][64];
    __shared__ float pbuf[ROWS][256];
    __shared__ float red[8];
    __shared__ float rmax_s[ROWS];
    __shared__ float rinv_s[ROWS];
    __shared__ float e1s[ROWS];

    int tid  = threadIdx.x;
    int lane = tid & 31;
    int warp = tid >> 5;
    int i0 = blockIdx.x * ROWS;

    for (int j = tid; j < N_KC; j += 256) e2s[j] = e2[j];
    if (tid < ROWS) e1s[tid] = e1[i0 + tid];
    __syncthreads();

    // ----- per-row softmax stats + adjacency bit-pack -----
    for (int i = 0; i < ROWS; i++) {
        float e1i = e1s[i];
        const int* arow = adj + (size_t)(i0 + i) * N_KC;
        float lmax = -INFINITY;
        #pragma unroll
        for (int it = 0; it < NCH; it++) {
            int j = tid + it * 256;
            int av = (j < N_KC) ? arow[j] : 0;
            unsigned bal = __ballot_sync(0xFFFFFFFFu, av > 0);
            if (lane == 0) maskb[i][warp + it * 8] = bal;
            if (av > 0) {
                float v = e1i + e2s[j];
                v = v > 0.f ? v : ALPHA * v;
                lmax = fmaxf(lmax, v);
            }
        }
        #pragma unroll
        for (int o = 16; o; o >>= 1) lmax = fmaxf(lmax, __shfl_xor_sync(0xFFFFFFFFu, lmax, o));
        if (lane == 0) red[warp] = lmax;
        __syncthreads();
        if (warp == 0) {
            float m = (lane < 8) ? red[lane] : -INFINITY;
            #pragma unroll
            for (int o = 4; o; o >>= 1) m = fmaxf(m, __shfl_xor_sync(0xFFFFFFFFu, m, o));
            if (lane == 0) red[0] = m;
        }
        __syncthreads();
        float rmax = red[0];
        __syncthreads();

        float lsum = 0.f;
        if (rmax > -INFINITY) {
            #pragma unroll
            for (int it = 0; it < NCH; it++) {
                int j = tid + it * 256;
                if (j < N_KC) {
                    unsigned bit = (maskb[i][j >> 5] >> (j & 31)) & 1u;
                    if (bit) {
                        float v = e1i + e2s[j];
                        v = v > 0.f ? v : ALPHA * v;
                        lsum += __expf(v - rmax);
                    }
                }
            }
        }
        #pragma unroll
        for (int o = 16; o; o >>= 1) lsum += __shfl_xor_sync(0xFFFFFFFFu, lsum, o);
        if (lane == 0) red[warp] = lsum;
        __syncthreads();
        if (warp == 0 && lane == 0) {
            float s = 0.f;
            for (int w = 0; w < 8; w++) s += red[w];
            rmax_s[i] = rmax;
            // degenerate row (no edges): reference softmax is uniform 1/N_KC
            rinv_s[i] = (rmax > -INFINITY) ? 1.0f / s : -1.0f;
        }
        __syncthreads();
    }

    // ----- aggregation: acc[i] = sum_j p_ij * kcWh[j, tid] -----
    float acc[ROWS];
    #pragma unroll
    for (int i = 0; i < ROWS; i++) acc[i] = 0.f;

    for (int c = 0; c < NCH; c++) {
        int j0 = c * 256;
        int j = j0 + tid;
        if (j < N_KC) {
            float e2j = e2s[j];
            #pragma unroll
            for (int i = 0; i < ROWS; i++) {
                float rinv = rinv_s[i];
                float p;
                if (rinv < 0.f) {
                    p = 1.0f / N_KC;
                } else {
                    unsigned bit = (maskb[i][j >> 5] >> (j & 31)) & 1u;
                    float v = e1s[i] + e2j;
                    v = v > 0.f ? v : ALPHA * v;
                    p = bit ? __expf(v - rmax_s[i]) * rinv : 0.f;
                }
                pbuf[i][tid] = p;
            }
        } else {
            #pragma unroll
            for (int i = 0; i < ROWS; i++) pbuf[i][tid] = 0.f;
        }
        __syncthreads();
        int lim = min(256, N_KC - j0);   // 256 or 208; both % 4 == 0
        for (int jj = 0; jj < lim; jj += 4) {
            float w0 = kcWh[(size_t)(j0 + jj + 0) * OUT_F + tid];
            float w1 = kcWh[(size_t)(j0 + jj + 1) * OUT_F + tid];
            float w2 = kcWh[(size_t)(j0 + jj + 2) * OUT_F + tid];
            float w3 = kcWh[(size_t)(j0 + jj + 3) * OUT_F + tid];
            #pragma unroll
            for (int i = 0; i < ROWS; i++) {
                float4 p4 = *(const float4*)&pbuf[i][jj];
                acc[i] = fmaf(p4.x, w0, acc[i]);
                acc[i] = fmaf(p4.y, w1, acc[i]);
                acc[i] = fmaf(p4.z, w2, acc[i]);
                acc[i] = fmaf(p4.w, w3, acc[i]);
            }
        }
        __syncthreads();
    }

    #pragma unroll
    for (int i = 0; i < ROWS; i++) {
        int gi = i0 + i;
        float nk = acc[i];
        feat[(size_t)gi * (2 * OUT_F) + tid]          = nk;
        feat[(size_t)gi * (2 * OUT_F) + OUT_F + tid]  = nk * exEh[(size_t)gi * OUT_F + tid];
    }
}

// ---------------- launch ----------------
extern "C" void kernel_launch(void* const* d_in, const int* in_sizes, int n_in,
                              void* d_out, int out_size)
{
    const float* ex   = (const float*)d_in[0];
    const float* kc   = (const float*)d_in[1];
    const int*   adj  = (const int*)d_in[2];
    const float* W1   = (const float*)d_in[3];
    const float* E    = (const float*)d_in[4];
    const float* a    = (const float*)d_in[5];
    const float* rd_w = (const float*)d_in[6];
    const float* rd_b = (const float*)d_in[7];
    float* out = (float*)d_out;

    float *kcWh, *exEh, *feat, *e1, *e2, *v1, *v2, *rdT;
    cudaGetSymbolAddress((void**)&kcWh, g_kcWh);
    cudaGetSymbolAddress((void**)&exEh, g_exEh);
    cudaGetSymbolAddress((void**)&feat, g_feat);
    cudaGetSymbolAddress((void**)&e1, g_e1);
    cudaGetSymbolAddress((void**)&e2, g_e2);
    cudaGetSymbolAddress((void**)&v1, g_v1);
    cudaGetSymbolAddress((void**)&v2, g_v2);
    cudaGetSymbolAddress((void**)&rdT, g_rdT);

    // 1. v1, v2, rd_w transpose
    prep_kernel<<<1 + (2 * OUT_F * OUT_F + 255) / 256, 256>>>(W1, a, rd_w);

    // 2. kc_Wh = kc_h @ W1   [2000,256]
    sgemm_kernel<<<dim3(OUT_F / GBN, (N_KC + GBM - 1) / GBM), 256>>>(
        kc, W1, kcWh, N_KC, OUT_F, IN_F, nullptr, 0);

    // 3. e1 = ex @ v1, e2 = kc @ v2
    rowdot_kernel<<<(N_E * 32 + 255) / 256, 256>>>(ex, v1, e1, N_E);
    rowdot_kernel<<<(N_KC * 32 + 255) / 256, 256>>>(kc, v2, e2, N_KC);

    // 4. ex_Eh = ex @ E   [10000,256]
    sgemm_kernel<<<dim3(OUT_F / GBN, (N_E + GBM - 1) / GBM), 256>>>(
        ex, E, exEh, N_E, OUT_F, IN_F, nullptr, 0);

    // 5. fused attention -> feat [10000, 512]
    attn_kernel<<<N_E / ROWS, 256>>>(e1, e2, adj, kcWh, exEh, feat);

    // 6. out = elu(feat @ rdT + rd_b)   [10000,256]
    sgemm_kernel<<<dim3(OUT_F / GBN, (N_E + GBM - 1) / GBM), 256>>>(
        feat, rdT, out, N_E, OUT_F, 2 * OUT_F, rd_b, 1);
}

// round 5
// speedup vs baseline: 1.5382x; 1.5382x over previous
#include <cuda_runtime.h>
#include <cuda_bf16.h>
#include <math.h>
#include <stdint.h>

#define IN_F   256
#define OUT_F  256
#define N_E    10000
#define N_KC   2000
#define ALPHA  0.2f

#define MT      64            // rows per attention block tile
#define KC      32            // j per K-chunk
#define NKC_PAD 2048
#define NCHUNK  (NKC_PAD / KC)   // 64
#define RSTRIDE 80            // bytes per smem tile row (64B data + 16B pad)

// ---------------- scratch (static __device__, no allocation) ----------------
__device__ float g_kcWh[N_KC * OUT_F];     // 2 MB
__device__ float g_exEh[N_E * OUT_F];      // 10 MB
__device__ float g_feat[N_E * 2 * OUT_F];  // 20 MB
__device__ float g_e1[N_E];
__device__ float g_e2[N_KC];
__device__ float g_v1[IN_F];
__device__ float g_v2[IN_F];
__device__ float g_rdT[2 * OUT_F * OUT_F]; // rd_w transposed: [512][256]
// chunk-blocked transposed kcWh: index ((chunk*256 + n)*KC + (j%KC))
__device__ __nv_bfloat16 g_kcWhT_hi[OUT_F * NKC_PAD];
__device__ __nv_bfloat16 g_kcWhT_lo[OUT_F * NKC_PAD];
__device__ float g_colmean[OUT_F];
// separable-exp tables
__device__ float g_Ae[N_E];        // exp(e1)
__device__ float g_Ce[N_E];        // exp(ALPHA*e1)
__device__ float g_Bf[NKC_PAD];    // exp(e2), 0 pad
__device__ float g_Df[NKC_PAD];    // exp(ALPHA*e2), 0 pad
__device__ float g_e2p[NKC_PAD];   // e2, 0 pad

// ---------------- helpers ----------------
static __device__ __forceinline__ uint32_t smem_u32(const void* p) {
    uint32_t a;
    asm("{ .reg .u64 t; cvta.to.shared.u64 t, %1; cvt.u32.u64 %0, t; }" : "=r"(a) : "l"(p));
    return a;
}
#define LDSM_X4(R0,R1,R2,R3,ADDR) \
    asm volatile("ldmatrix.sync.aligned.m8n8.x4.shared.b16 {%0,%1,%2,%3}, [%4];" \
                 : "=r"(R0),"=r"(R1),"=r"(R2),"=r"(R3) : "r"(ADDR))

static __device__ __forceinline__ void mma_bf16(float* c, const uint32_t* a, const uint32_t* b) {
    asm volatile(
        "mma.sync.aligned.m16n8k16.row.col.f32.bf16.bf16.f32 "
        "{%0,%1,%2,%3}, {%4,%5,%6,%7}, {%8,%9}, {%0,%1,%2,%3};"
        : "+f"(c[0]), "+f"(c[1]), "+f"(c[2]), "+f"(c[3])
        : "r"(a[0]), "r"(a[1]), "r"(a[2]), "r"(a[3]), "r"(b[0]), "r"(b[1]));
}

// dyn smem layout (bytes)
#define OFF_BHI 0                         // 256*80 = 20480
#define OFF_BLO 20480
#define OFF_AHI 40960                     // 64*80 = 5120
#define OFF_ALO 46080
#define OFF_E2  51200                     // 2048*4
#define OFF_BF  59392
#define OFF_DF  67584
#define OFF_E1  75776                     // 64*4
#define OFF_AE  76032
#define OFF_CE  76288
#define OFF_RS  76544                     // 256*4
#define OFF_RSF 77568                     // 64*4
#define SMEM_ATTN 77824

// ---------------- prep: v1 = W1@a1, v2 = W1@a2, rdT = rd_w^T ----------------
__global__ void prep_kernel(const float* __restrict__ W1, const float* __restrict__ a,
                            const float* __restrict__ rd_w)
{
    int b = blockIdx.x;
    if (b == 0) {
        int k = threadIdx.x;
        float s1 = 0.f, s2 = 0.f;
        #pragma unroll 8
        for (int j = 0; j < OUT_F; j++) {
            float w = W1[k * OUT_F + j];
            s1 += w * a[j];
            s2 += w * a[OUT_F + j];
        }
        g_v1[k] = s1;
        g_v2[k] = s2;
    } else {
        int idx = (b - 1) * 256 + threadIdx.x;
        if (idx < 2 * OUT_F * OUT_F) {
            int k = idx >> 8;
            int n = idx & 255;
            g_rdT[idx] = rd_w[n * (2 * OUT_F) + k];
        }
    }
}

// ---------------- row dot ----------------
__global__ void rowdot_kernel(const float* __restrict__ X, const float* __restrict__ v,
                              float* __restrict__ out, int M)
{
    int gwarp = (blockIdx.x * blockDim.x + threadIdx.x) >> 5;
    int lane = threadIdx.x & 31;
    if (gwarp >= M) return;
    const float* row = X + (size_t)gwarp * IN_F;
    float s = 0.f;
    #pragma unroll
    for (int k = lane; k < IN_F; k += 32) s += row[k] * v[k];
    #pragma unroll
    for (int o = 16; o; o >>= 1) s += __shfl_xor_sync(0xFFFFFFFFu, s, o);
    if (lane == 0) out[gwarp] = s;
}

// ---------------- separable-exp tables ----------------
__global__ void expprep_kernel()
{
    int i = blockIdx.x * 256 + threadIdx.x;
    if (i < N_E) {
        float v = g_e1[i];
        g_Ae[i] = __expf(v);
        g_Ce[i] = __expf(ALPHA * v);
    }
    if (i < NKC_PAD) {
        bool ok = i < N_KC;
        float v = ok ? g_e2[i] : 0.f;
        g_e2p[i] = v;
        g_Bf[i] = ok ? __expf(v) : 0.f;
        g_Df[i] = ok ? __expf(ALPHA * v) : 0.f;
    }
}

// ---------------- transpose+convert kcWh -> chunk-blocked bf16 hi/lo ----------------
__global__ void conv_kernel(const float* __restrict__ kcWh)
{
    __shared__ float t[32][33];
    int jb = blockIdx.x * 32, nb = blockIdx.y * 32;
    int tx = threadIdx.x & 31, ty = threadIdx.x >> 5;
    #pragma unroll
    for (int rr = 0; rr < 32; rr += 8) {
        int j = jb + ty + rr, n = nb + tx;
        t[ty + rr][tx] = (j < N_KC) ? kcWh[(size_t)j * OUT_F + n] : 0.f;
    }
    __syncthreads();
    #pragma unroll
    for (int rr = 0; rr < 32; rr += 8) {
        int n = nb + ty + rr;
        float v = t[tx][ty + rr];
        __nv_bfloat16 h = __float2bfloat16(v);
        __nv_bfloat16 l = __float2bfloat16(v - __bfloat162float(h));
        size_t di = ((size_t)(jb >> 5) * 256 + n) * KC + tx;   // KC==32
        g_kcWhT_hi[di] = h;
        g_kcWhT_lo[di] = l;
    }
}

__global__ void colmean_kernel(const float* __restrict__ kcWh)
{
    int n = threadIdx.x;
    float s = 0.f;
    for (int j = 0; j < N_KC; j++) s += kcWh[(size_t)j * OUT_F + n];
    g_colmean[n] = s * (1.0f / N_KC);
}

// ---------------- tiled SGEMM ----------------
#define GBM 128
#define GBN 64
#define GBK 16
__global__ __launch_bounds__(256) void sgemm_kernel(
    const float* __restrict__ A, const float* __restrict__ B, float* __restrict__ C,
    int M, int N, int K, const float* __restrict__ bias, int epi)
{
    __shared__ float As[GBK][GBM];
    __shared__ float Bs[GBK][GBN];
    int tid = threadIdx.x;
    int bm = blockIdx.y * GBM;
    int bn = blockIdx.x * GBN;
    int tx = tid & 15;
    int ty = tid >> 4;
    float acc[8][4];
    #pragma unroll
    for (int m = 0; m < 8; m++)
        #pragma unroll
        for (int n = 0; n < 4; n++) acc[m][n] = 0.f;

    int brow = tid >> 4;
    int bcol = (tid & 15) * 4;

    for (int k0 = 0; k0 < K; k0 += GBK) {
        #pragma unroll
        for (int l = 0; l < 2; l++) {
            int f = tid + l * 256;
            int row = f >> 2;
            int col = (f & 3) * 4;
            float4 av;
            if (bm + row < M)
                av = *(const float4*)&A[(size_t)(bm + row) * K + k0 + col];
            else
                av = make_float4(0.f, 0.f, 0.f, 0.f);
            As[col + 0][row] = av.x;
            As[col + 1][row] = av.y;
            As[col + 2][row] = av.z;
            As[col + 3][row] = av.w;
        }
        *(float4*)&Bs[brow][bcol] = *(const float4*)&B[(size_t)(k0 + brow) * N + bn + bcol];
        __syncthreads();
        #pragma unroll
        for (int k = 0; k < GBK; k++) {
            float4 a0 = *(const float4*)&As[k][ty * 8];
            float4 a1 = *(const float4*)&As[k][ty * 8 + 4];
            float4 b0 = *(const float4*)&Bs[k][tx * 4];
            float ar[8] = {a0.x, a0.y, a0.z, a0.w, a1.x, a1.y, a1.z, a1.w};
            float br[4] = {b0.x, b0.y, b0.z, b0.w};
            #pragma unroll
            for (int m = 0; m < 8; m++)
                #pragma unroll
                for (int n = 0; n < 4; n++)
                    acc[m][n] = fmaf(ar[m], br[n], acc[m][n]);
        }
        __syncthreads();
    }
    #pragma unroll
    for (int m = 0; m < 8; m++) {
        int row = bm + ty * 8 + m;
        if (row >= M) continue;
        #pragma unroll
        for (int n = 0; n < 4; n++) {
            int col = bn + tx * 4 + n;
            float v = acc[m][n];
            if (epi == 1) {
                v += bias[col];
                v = v > 0.f ? v : expm1f(v);
            }
            C[(size_t)row * N + col] = v;
        }
    }
}

// ---------------- attention: P-gen + warp-level bf16 hi/lo mma.sync ----------------
static __device__ __forceinline__ float pgen(int m, float e1v, float Ai, float Ci,
    const float* e2f, const float* bfv, const float* dfv, int j)
{
    float s = e1v + e2f[j];
    float pv = (s > 0.f) ? Ai * bfv[j] : Ci * dfv[j];
    return (m > 0) ? pv : 0.f;
}

static __device__ __forceinline__ void psplit_store(char* ph, char* pl, int t,
                                                    float p0, float p1)
{
    __nv_bfloat16 h0 = __float2bfloat16(p0);
    __nv_bfloat16 h1 = __float2bfloat16(p1);
    __nv_bfloat16 l0 = __float2bfloat16(p0 - __bfloat162float(h0));
    __nv_bfloat16 l1 = __float2bfloat16(p1 - __bfloat162float(h1));
    __nv_bfloat162 hh = __halves2bfloat162(h0, h1);
    __nv_bfloat162 ll = __halves2bfloat162(l0, l1);
    *(uint32_t*)(ph + 4 * t) = *(uint32_t*)&hh;
    *(uint32_t*)(pl + 4 * t) = *(uint32_t*)&ll;
}

__global__ __launch_bounds__(256, 2) void attn_mma_kernel(
    const float* __restrict__ e1, const int* __restrict__ adj,
    const float* __restrict__ exEh, float* __restrict__ feat)
{
    extern __shared__ char smem[];
    uint32_t sb = smem_u32(smem);
    float* e2f = (float*)(smem + OFF_E2);
    float* bfv = (float*)(smem + OFF_BF);
    float* dfv = (float*)(smem + OFF_DF);
    float* e1s = (float*)(smem + OFF_E1);
    float* Aes = (float*)(smem + OFF_AE);
    float* Ces = (float*)(smem + OFF_CE);

    int tid = threadIdx.x, lane = tid & 31, wid = tid >> 5;
    int i0 = blockIdx.x * MT;

    for (int j = tid; j < NKC_PAD; j += 256) {
        e2f[j] = g_e2p[j];
        bfv[j] = g_Bf[j];
        dfv[j] = g_Df[j];
    }
    if (tid < MT) {
        int gi = i0 + tid;
        bool v = gi < N_E;
        e1s[tid] = v ? e1[gi] : 0.f;
        Aes[tid] = v ? g_Ae[gi] : 0.f;
        Ces[tid] = v ? g_Ce[gi] : 0.f;
    }
    __syncthreads();

    // P-gen identity: 4 threads per row, 8 j each
    int r = tid >> 2, q = tid & 3, jl0 = q * 8;
    int gi_r = i0 + r;
    const int* arow = adj + (size_t)(gi_r < N_E ? gi_r : 0) * N_KC;
    float e1v = e1s[r], Ai = Aes[r], Ci = Ces[r];
    float srow = 0.f;

    // warp tiling: 2 (M) x 4 (N); warp tile 32 x 64
    int wm = wid & 1, wn = wid >> 1;
    float acc[2][8][4];
    #pragma unroll
    for (int mt = 0; mt < 2; mt++)
        #pragma unroll
        for (int nb = 0; nb < 8; nb++)
            #pragma unroll
            for (int k = 0; k < 4; k++) acc[mt][nb][k] = 0.f;

    char* ph = smem + OFF_AHI + r * RSTRIDE + jl0 * 2;
    char* pl = smem + OFF_ALO + r * RSTRIDE + jl0 * 2;

    for (int c = 0; c < NCHUNK; c++) {
        int j0 = c * KC;
        // --- B tile: chunk-blocked global -> padded smem rows (contiguous copies)
        {
            const uint4* sh = (const uint4*)(g_kcWhT_hi + ((size_t)c * 256 + tid) * KC);
            const uint4* sl = (const uint4*)(g_kcWhT_lo + ((size_t)c * 256 + tid) * KC);
            char* dh = smem + OFF_BHI + tid * RSTRIDE;
            char* dl = smem + OFF_BLO + tid * RSTRIDE;
            #pragma unroll
            for (int t = 0; t < 4; t++) {
                *(uint4*)(dh + t * 16) = sh[t];
                *(uint4*)(dl + t * 16) = sl[t];
            }
        }
        // --- P tile generation (no exp: separable tables)
        if (j0 + KC <= N_KC) {
            const int4* ap = (const int4*)(arow + j0 + jl0);
            int4 a0 = ap[0], a1 = ap[1];
            int am[8] = {a0.x, a0.y, a0.z, a0.w, a1.x, a1.y, a1.z, a1.w};
            #pragma unroll
            for (int t = 0; t < 4; t++) {
                int j = j0 + jl0 + 2 * t;
                float p0 = pgen(am[2 * t],     e1v, Ai, Ci, e2f, bfv, dfv, j);
                float p1 = pgen(am[2 * t + 1], e1v, Ai, Ci, e2f, bfv, dfv, j + 1);
                srow += p0 + p1;
                psplit_store(ph, pl, t, p0, p1);
            }
        } else {
            #pragma unroll
            for (int t = 0; t < 4; t++) {
                int j = j0 + jl0 + 2 * t;
                int m0 = (j     < N_KC) ? arow[j]     : 0;
                int m1 = (j + 1 < N_KC) ? arow[j + 1] : 0;
                float p0 = pgen(m0, e1v, Ai, Ci, e2f, bfv, dfv, (j     < N_KC) ? j     : 0);
                float p1 = pgen(m1, e1v, Ai, Ci, e2f, bfv, dfv, (j + 1 < N_KC) ? j + 1 : 0);
                srow += p0 + p1;
                psplit_store(ph, pl, t, p0, p1);
            }
        }
        __syncthreads();

        // --- MMA phase: 3-product bf16 hi/lo
        #pragma unroll
        for (int ks = 0; ks < 2; ks++) {
            uint32_t ahi[2][4], alo[2][4], bfrag[8][2];
            int arowi = lane & 15;
            int akoff = (ks * 16 + ((lane >> 4) & 1) * 8) * 2;
            #pragma unroll
            for (int mt = 0; mt < 2; mt++) {
                uint32_t ad = sb + OFF_AHI + (wm * 32 + mt * 16 + arowi) * RSTRIDE + akoff;
                LDSM_X4(ahi[mt][0], ahi[mt][1], ahi[mt][2], ahi[mt][3], ad);
                ad += (OFF_ALO - OFF_AHI);
                LDSM_X4(alo[mt][0], alo[mt][1], alo[mt][2], alo[mt][3], ad);
            }
            int bnrow = (lane & 7) + ((lane >> 4) << 3);
            int bkoff = (ks * 16 + ((lane >> 3) & 1) * 8) * 2;
            #pragma unroll
            for (int nq = 0; nq < 4; nq++) {
                uint32_t bd = sb + OFF_BHI + (wn * 64 + nq * 16 + bnrow) * RSTRIDE + bkoff;
                LDSM_X4(bfrag[2 * nq][0], bfrag[2 * nq][1],
                        bfrag[2 * nq + 1][0], bfrag[2 * nq + 1][1], bd);
            }
            #pragma unroll
            for (int mt = 0; mt < 2; mt++)
                #pragma unroll
                for (int nb = 0; nb < 8; nb++)
                    mma_bf16(acc[mt][nb], ahi[mt], bfrag[nb]);   // Ahi*Bhi
            #pragma unroll
            for (int mt = 0; mt < 2; mt++)
                #pragma unroll
                for (int nb = 0; nb < 8; nb++)
                    mma_bf16(acc[mt][nb], alo[mt], bfrag[nb]);   // Alo*Bhi
            #pragma unroll
            for (int nq = 0; nq < 4; nq++) {
                uint32_t bd = sb + OFF_BLO + (wn * 64 + nq * 16 + bnrow) * RSTRIDE + bkoff;
                LDSM_X4(bfrag[2 * nq][0], bfrag[2 * nq][1],
                        bfrag[2 * nq + 1][0], bfrag[2 * nq + 1][1], bd);
            }
            #pragma unroll
            for (int mt = 0; mt < 2; mt++)
                #pragma unroll
                for (int nb = 0; nb < 8; nb++)
                    mma_bf16(acc[mt][nb], ahi[mt], bfrag[nb]);   // Ahi*Blo
        }
        __syncthreads();
    }

    // --- row-sum reduction
    ((float*)(smem + OFF_RS))[tid] = srow;
    __syncthreads();
    if (tid < MT) {
        const float* r4 = (const float*)(smem + OFF_RS) + tid * 4;
        ((float*)(smem + OFF_RSF))[tid] = (r4[0] + r4[1]) + (r4[2] + r4[3]);
    }
    __syncthreads();
    const float* rsF = (const float*)(smem + OFF_RSF);

    // --- epilogue: normalize + fused feat = [new_kc, new_kc * exEh]
    #pragma unroll
    for (int mt = 0; mt < 2; mt++) {
        #pragma unroll
        for (int nb = 0; nb < 8; nb++) {
            int row0 = wm * 32 + mt * 16 + (lane >> 2);
            int col  = wn * 64 + nb * 8 + (lane & 3) * 2;
            #pragma unroll
            for (int h = 0; h < 2; h++) {
                int rr = row0 + h * 8;
                int gi = i0 + rr;
                if (gi >= N_E) continue;
                float v0 = acc[mt][nb][2 * h];
                float v1 = acc[mt][nb][2 * h + 1];
                float rs = rsF[rr];
                float nk0, nk1;
                if (rs > 0.f) {
                    float ri = 1.f / rs;
                    nk0 = v0 * ri;
                    nk1 = v1 * ri;
                } else {
                    nk0 = g_colmean[col];
                    nk1 = g_colmean[col + 1];
                }
                size_t fb = (size_t)gi * (2 * OUT_F);
                float x0 = exEh[(size_t)gi * OUT_F + col];
                float x1 = exEh[(size_t)gi * OUT_F + col + 1];
                feat[fb + col]             = nk0;
                feat[fb + col + 1]         = nk1;
                feat[fb + OUT_F + col]     = nk0 * x0;
                feat[fb + OUT_F + col + 1] = nk1 * x1;
            }
        }
    }
}

// ---------------- launch ----------------
extern "C" void kernel_launch(void* const* d_in, const int* in_sizes, int n_in,
                              void* d_out, int out_size)
{
    const float* ex   = (const float*)d_in[0];
    const float* kc   = (const float*)d_in[1];
    const int*   adj  = (const int*)d_in[2];
    const float* W1   = (const float*)d_in[3];
    const float* E    = (const float*)d_in[4];
    const float* a    = (const float*)d_in[5];
    const float* rd_w = (const float*)d_in[6];
    const float* rd_b = (const float*)d_in[7];
    float* out = (float*)d_out;

    float *kcWh, *exEh, *feat, *e1, *e2, *v1, *v2, *rdT;
    cudaGetSymbolAddress((void**)&kcWh, g_kcWh);
    cudaGetSymbolAddress((void**)&exEh, g_exEh);
    cudaGetSymbolAddress((void**)&feat, g_feat);
    cudaGetSymbolAddress((void**)&e1, g_e1);
    cudaGetSymbolAddress((void**)&e2, g_e2);
    cudaGetSymbolAddress((void**)&v1, g_v1);
    cudaGetSymbolAddress((void**)&v2, g_v2);
    cudaGetSymbolAddress((void**)&rdT, g_rdT);

    cudaFuncSetAttribute(attn_mma_kernel,
                         cudaFuncAttributeMaxDynamicSharedMemorySize, SMEM_ATTN);

    // 1. v1, v2, rd_w transpose
    prep_kernel<<<1 + (2 * OUT_F * OUT_F + 255) / 256, 256>>>(W1, a, rd_w);

    // 2. kc_Wh = kc_h @ W1   [2000,256]
    sgemm_kernel<<<dim3(OUT_F / GBN, (N_KC + GBM - 1) / GBM), 256>>>(
        kc, W1, kcWh, N_KC, OUT_F, IN_F, nullptr, 0);

    // 3. e1 = ex @ v1, e2 = kc @ v2, then exp tables
    rowdot_kernel<<<(N_E * 32 + 255) / 256, 256>>>(ex, v1, e1, N_E);
    rowdot_kernel<<<(N_KC * 32 + 255) / 256, 256>>>(kc, v2, e2, N_KC);
    expprep_kernel<<<(N_E + 255) / 256, 256>>>();

    // 4. ex_Eh = ex @ E   [10000,256]
    sgemm_kernel<<<dim3(OUT_F / GBN, (N_E + GBM - 1) / GBM), 256>>>(
        ex, E, exEh, N_E, OUT_F, IN_F, nullptr, 0);

    // 5. kcWh -> chunk-blocked transposed bf16 hi/lo + column mean
    conv_kernel<<<dim3(NKC_PAD / 32, OUT_F / 32), 256>>>(kcWh);
    colmean_kernel<<<1, OUT_F>>>(kcWh);

    // 6. tensor-core (mma.sync) attention -> feat [10000, 512]
    attn_mma_kernel<<<(N_E + MT - 1) / MT, 256, SMEM_ATTN>>>(e1, adj, exEh, feat);

    // 7. out = elu(feat @ rdT + rd_b)   [10000,256]
    sgemm_kernel<<<dim3(OUT_F / GBN, (N_E + GBM - 1) / GBM), 256>>>(
        feat, rdT, out, N_E, OUT_F, 2 * OUT_F, rd_b, 1);
}

// round 6
// speedup vs baseline: 1.6920x; 1.1000x over previous
#include <cuda_runtime.h>
#include <cuda_bf16.h>
#include <math.h>
#include <stdint.h>

#define IN_F   256
#define OUT_F  256
#define N_E    10000
#define N_KC   2000
#define ALPHA  0.2f

#define MT      64            // rows per attention block tile
#define KC      32            // j per K-chunk
#define NKC_PAD 2048
#define NCHUNK  (NKC_PAD / KC)   // 64
#define RSTRIDE 80            // bytes per smem tile row (64B data + 16B pad)

typedef __nv_bfloat16 bf16;

// ---------------- scratch (static __device__, no allocation) ----------------
__device__ float g_kcWh[N_KC * OUT_F];
__device__ float g_exEh[N_E * OUT_F];
__device__ float g_e1[N_E];
__device__ float g_e2[N_KC];
__device__ float g_v1[IN_F];
__device__ float g_v2[IN_F];
// chunk-blocked transposed kcWh for attention B: ((chunk*256 + n)*KC + j%KC)
__device__ bf16 g_kcWhT_hi[OUT_F * NKC_PAD];
__device__ bf16 g_kcWhT_lo[OUT_F * NKC_PAD];
__device__ float g_colmean[OUT_F];
// separable-exp tables
__device__ float g_Ae[N_E];
__device__ float g_Ce[N_E];
__device__ float g_Bf[NKC_PAD];
__device__ float g_Df[NKC_PAD];
__device__ float g_e2p[NKC_PAD];
// hi/lo split operands for mma GEMMs
__device__ bf16 g_exhi[N_E * IN_F];
__device__ bf16 g_exlo[N_E * IN_F];
__device__ bf16 g_kchi[N_KC * IN_F];
__device__ bf16 g_kclo[N_KC * IN_F];
__device__ bf16 g_W1Thi[OUT_F * IN_F];   // [n][k]
__device__ bf16 g_W1Tlo[OUT_F * IN_F];
__device__ bf16 g_EThi[OUT_F * IN_F];    // [n][k]
__device__ bf16 g_ETlo[OUT_F * IN_F];
__device__ bf16 g_rdwhi[OUT_F * 2 * OUT_F]; // rd_w is [n=256][k=512]
__device__ bf16 g_rdwlo[OUT_F * 2 * OUT_F];
__device__ bf16 g_feathi[N_E * 2 * OUT_F];  // attention writes feat hi/lo
__device__ bf16 g_featlo[N_E * 2 * OUT_F];

// ---------------- helpers ----------------
static __device__ __forceinline__ uint32_t smem_u32(const void* p) {
    uint32_t a;
    asm("{ .reg .u64 t; cvta.to.shared.u64 t, %1; cvt.u32.u64 %0, t; }" : "=r"(a) : "l"(p));
    return a;
}
#define LDSM_X4(R0,R1,R2,R3,ADDR) \
    asm volatile("ldmatrix.sync.aligned.m8n8.x4.shared.b16 {%0,%1,%2,%3}, [%4];" \
                 : "=r"(R0),"=r"(R1),"=r"(R2),"=r"(R3) : "r"(ADDR))

static __device__ __forceinline__ void mma_bf16(float* c, const uint32_t* a, const uint32_t* b) {
    asm volatile(
        "mma.sync.aligned.m16n8k16.row.col.f32.bf16.bf16.f32 "
        "{%0,%1,%2,%3}, {%4,%5,%6,%7}, {%8,%9}, {%0,%1,%2,%3};"
        : "+f"(c[0]), "+f"(c[1]), "+f"(c[2]), "+f"(c[3])
        : "r"(a[0]), "r"(a[1]), "r"(a[2]), "r"(a[3]), "r"(b[0]), "r"(b[1]));
}
static __device__ __forceinline__ void fsplit(float v, bf16& h, bf16& l) {
    h = __float2bfloat16(v);
    l = __float2bfloat16(v - __bfloat162float(h));
}
static __device__ __forceinline__ uint32_t pack2(bf16 a, bf16 b) {
    __nv_bfloat162 t = __halves2bfloat162(a, b);
    return *(uint32_t*)&t;
}

// ---------------- prep: v1 = W1@a1, v2 = W1@a2 ----------------
__global__ void prep_kernel(const float* __restrict__ W1, const float* __restrict__ a)
{
    int k = threadIdx.x;
    float s1 = 0.f, s2 = 0.f;
    #pragma unroll 8
    for (int j = 0; j < OUT_F; j++) {
        float w = W1[k * OUT_F + j];
        s1 += w * a[j];
        s2 += w * a[OUT_F + j];
    }
    g_v1[k] = s1;
    g_v2[k] = s2;
}

// ---------------- elementwise hi/lo split ----------------
__global__ void split_kernel(const float* __restrict__ src, bf16* __restrict__ hi,
                             bf16* __restrict__ lo, int n)
{
    int i = blockIdx.x * 256 + threadIdx.x;
    if (i * 4 + 3 < n) {
        float4 v = *(const float4*)(src + i * 4);
        bf16 h0, l0, h1, l1, h2, l2, h3, l3;
        fsplit(v.x, h0, l0); fsplit(v.y, h1, l1);
        fsplit(v.z, h2, l2); fsplit(v.w, h3, l3);
        *(uint32_t*)(hi + i * 4)     = pack2(h0, h1);
        *(uint32_t*)(hi + i * 4 + 2) = pack2(h2, h3);
        *(uint32_t*)(lo + i * 4)     = pack2(l0, l1);
        *(uint32_t*)(lo + i * 4 + 2) = pack2(l2, l3);
    }
}

// ---------------- transpose + split: src [K][N] -> hi/lo [N][K] ----------------
__global__ void tsplit_kernel(const float* __restrict__ src, bf16* __restrict__ hi,
                              bf16* __restrict__ lo, int K, int N)
{
    __shared__ float t[32][33];
    int kb = blockIdx.x * 32, nb = blockIdx.y * 32;
    int tx = threadIdx.x & 31, ty = threadIdx.x >> 5;
    #pragma unroll
    for (int rr = 0; rr < 32; rr += 8)
        t[ty + rr][tx] = src[(size_t)(kb + ty + rr) * N + nb + tx];
    __syncthreads();
    #pragma unroll
    for (int rr = 0; rr < 32; rr += 8) {
        int n = nb + ty + rr;
        bf16 h, l;
        fsplit(t[tx][ty + rr], h, l);
        hi[(size_t)n * K + kb + tx] = h;
        lo[(size_t)n * K + kb + tx] = l;
    }
}

// ---------------- row dot ----------------
__global__ void rowdot_kernel(const float* __restrict__ X, const float* __restrict__ v,
                              float* __restrict__ out, int M)
{
    int gwarp = (blockIdx.x * blockDim.x + threadIdx.x) >> 5;
    int lane = threadIdx.x & 31;
    if (gwarp >= M) return;
    const float* row = X + (size_t)gwarp * IN_F;
    float s = 0.f;
    #pragma unroll
    for (int k = lane; k < IN_F; k += 32) s += row[k] * v[k];
    #pragma unroll
    for (int o = 16; o; o >>= 1) s += __shfl_xor_sync(0xFFFFFFFFu, s, o);
    if (lane == 0) out[gwarp] = s;
}

// ---------------- separable-exp tables ----------------
__global__ void expprep_kernel()
{
    int i = blockIdx.x * 256 + threadIdx.x;
    if (i < N_E) {
        float v = g_e1[i];
        g_Ae[i] = __expf(v);
        g_Ce[i] = __expf(ALPHA * v);
    }
    if (i < NKC_PAD) {
        bool ok = i < N_KC;
        float v = ok ? g_e2[i] : 0.f;
        g_e2p[i] = v;
        g_Bf[i] = ok ? __expf(v) : 0.f;
        g_Df[i] = ok ? __expf(ALPHA * v) : 0.f;
    }
}

// ---------------- transpose+convert kcWh -> chunk-blocked bf16 hi/lo ----------------
__global__ void conv_kernel(const float* __restrict__ kcWh)
{
    __shared__ float t[32][33];
    int jb = blockIdx.x * 32, nb = blockIdx.y * 32;
    int tx = threadIdx.x & 31, ty = threadIdx.x >> 5;
    #pragma unroll
    for (int rr = 0; rr < 32; rr += 8) {
        int j = jb + ty + rr, n = nb + tx;
        t[ty + rr][tx] = (j < N_KC) ? kcWh[(size_t)j * OUT_F + n] : 0.f;
    }
    __syncthreads();
    #pragma unroll
    for (int rr = 0; rr < 32; rr += 8) {
        int n = nb + ty + rr;
        bf16 h, l;
        fsplit(t[tx][ty + rr], h, l);
        size_t di = ((size_t)(jb >> 5) * 256 + n) * KC + tx;
        g_kcWhT_hi[di] = h;
        g_kcWhT_lo[di] = l;
    }
}

__global__ void colmean_kernel(const float* __restrict__ kcWh)
{
    int n = threadIdx.x;
    float s = 0.f;
    for (int j = 0; j < N_KC; j++) s += kcWh[(size_t)j * OUT_F + n];
    g_colmean[n] = s * (1.0f / N_KC);
}

// ---------------- bf16 hi/lo tensor-core GEMM ----------------
// C[M][N] = A @ B^T where A given as hi/lo [M][K], B given as hi/lo [N][K].
// Block 128x128, 8 warps (4 M x 2 N), warp tile 32x64. K % 32 == 0, N % 128 == 0.
// epi==1: C = elu(C + bias)
#define HOF_AH 0
#define HOF_AL 10240
#define HOF_BH 20480
#define HOF_BL 30720
__global__ __launch_bounds__(256, 2) void hgemm_kernel(
    const bf16* __restrict__ Ahi, const bf16* __restrict__ Alo,
    const bf16* __restrict__ Bhi, const bf16* __restrict__ Blo,
    float* __restrict__ C, int M, int N, int K,
    const float* __restrict__ bias, int epi)
{
    __shared__ char smem[40960];
    uint32_t sb = smem_u32(smem);
    int tid = threadIdx.x, lane = tid & 31, wid = tid >> 5;
    int bm = blockIdx.y * 128, bn = blockIdx.x * 128;
    int wm = wid >> 1, wn = wid & 1;

    float acc[2][8][4];
    #pragma unroll
    for (int mt = 0; mt < 2; mt++)
        #pragma unroll
        for (int nb = 0; nb < 8; nb++)
            #pragma unroll
            for (int k = 0; k < 4; k++) acc[mt][nb][k] = 0.f;

    int crow = tid >> 1, chalf = tid & 1;   // copy role: 2 threads/row, 32B each
    bool arow_ok = (bm + crow) < M;
    const uint4 zero4 = make_uint4(0, 0, 0, 0);

    for (int k0 = 0; k0 < K; k0 += 32) {
        // A tiles
        {
            char* dh = smem + HOF_AH + crow * RSTRIDE + chalf * 32;
            char* dl = smem + HOF_AL + crow * RSTRIDE + chalf * 32;
            if (arow_ok) {
                const uint4* sh = (const uint4*)(Ahi + (size_t)(bm + crow) * K + k0 + chalf * 16);
                const uint4* sl = (const uint4*)(Alo + (size_t)(bm + crow) * K + k0 + chalf * 16);
                ((uint4*)dh)[0] = sh[0]; ((uint4*)dh)[1] = sh[1];
                ((uint4*)dl)[0] = sl[0]; ((uint4*)dl)[1] = sl[1];
            } else {
                ((uint4*)dh)[0] = zero4; ((uint4*)dh)[1] = zero4;
                ((uint4*)dl)[0] = zero4; ((uint4*)dl)[1] = zero4;
            }
        }
        // B tiles
        {
            const uint4* sh = (const uint4*)(Bhi + (size_t)(bn + crow) * K + k0 + chalf * 16);
            const uint4* sl = (const uint4*)(Blo + (size_t)(bn + crow) * K + k0 + chalf * 16);
            char* dh = smem + HOF_BH + crow * RSTRIDE + chalf * 32;
            char* dl = smem + HOF_BL + crow * RSTRIDE + chalf * 32;
            ((uint4*)dh)[0] = sh[0]; ((uint4*)dh)[1] = sh[1];
            ((uint4*)dl)[0] = sl[0]; ((uint4*)dl)[1] = sl[1];
        }
        __syncthreads();

        #pragma unroll
        for (int ks = 0; ks < 2; ks++) {
            uint32_t ahi[2][4], alo[2][4], bfrag[8][2];
            int arowi = lane & 15;
            int akoff = (ks * 16 + ((lane >> 4) & 1) * 8) * 2;
            #pragma unroll
            for (int mt = 0; mt < 2; mt++) {
                uint32_t ad = sb + HOF_AH + (wm * 32 + mt * 16 + arowi) * RSTRIDE + akoff;
                LDSM_X4(ahi[mt][0], ahi[mt][1], ahi[mt][2], ahi[mt][3], ad);
                ad += (HOF_AL - HOF_AH);
                LDSM_X4(alo[mt][0], alo[mt][1], alo[mt][2], alo[mt][3], ad);
            }
            int bnrow = (lane & 7) + ((lane >> 4) << 3);
            int bkoff = (ks * 16 + ((lane >> 3) & 1) * 8) * 2;
            #pragma unroll
            for (int nq = 0; nq < 4; nq++) {
                uint32_t bd = sb + HOF_BH + (wn * 64 + nq * 16 + bnrow) * RSTRIDE + bkoff;
                LDSM_X4(bfrag[2 * nq][0], bfrag[2 * nq][1],
                        bfrag[2 * nq + 1][0], bfrag[2 * nq + 1][1], bd);
            }
            #pragma unroll
            for (int mt = 0; mt < 2; mt++)
                #pragma unroll
                for (int nb = 0; nb < 8; nb++)
                    mma_bf16(acc[mt][nb], ahi[mt], bfrag[nb]);
            #pragma unroll
            for (int mt = 0; mt < 2; mt++)
                #pragma unroll
                for (int nb = 0; nb < 8; nb++)
                    mma_bf16(acc[mt][nb], alo[mt], bfrag[nb]);
            #pragma unroll
            for (int nq = 0; nq < 4; nq++) {
                uint32_t bd = sb + HOF_BL + (wn * 64 + nq * 16 + bnrow) * RSTRIDE + bkoff;
                LDSM_X4(bfrag[2 * nq][0], bfrag[2 * nq][1],
                        bfrag[2 * nq + 1][0], bfrag[2 * nq + 1][1], bd);
            }
            #pragma unroll
            for (int mt = 0; mt < 2; mt++)
                #pragma unroll
                for (int nb = 0; nb < 8; nb++)
                    mma_bf16(acc[mt][nb], ahi[mt], bfrag[nb]);
        }
        __syncthreads();
    }

    #pragma unroll
    for (int mt = 0; mt < 2; mt++) {
        #pragma unroll
        for (int nb = 0; nb < 8; nb++) {
            int row0 = wm * 32 + mt * 16 + (lane >> 2);
            int col = bn + wn * 64 + nb * 8 + (lane & 3) * 2;
            #pragma unroll
            for (int h = 0; h < 2; h++) {
                int r = bm + row0 + h * 8;
                if (r >= M) continue;
                float v0 = acc[mt][nb][2 * h];
                float v1 = acc[mt][nb][2 * h + 1];
                if (epi == 1) {
                    v0 += bias[col];
                    v1 += bias[col + 1];
                    v0 = v0 > 0.f ? v0 : expm1f(v0);
                    v1 = v1 > 0.f ? v1 : expm1f(v1);
                }
                C[(size_t)r * N + col]     = v0;
                C[(size_t)r * N + col + 1] = v1;
            }
        }
    }
}

// ---------------- attention: P-gen + warp-level bf16 hi/lo mma.sync ----------------
// dyn smem layout (bytes)
#define OFF_BHI 0
#define OFF_BLO 20480
#define OFF_AHI 40960
#define OFF_ALO 46080
#define OFF_E2  51200
#define OFF_BF  59392
#define OFF_DF  67584
#define OFF_E1  75776
#define OFF_AE  76032
#define OFF_CE  76288
#define OFF_RS  76544
#define OFF_RSF 77568
#define SMEM_ATTN 77824

static __device__ __forceinline__ float pgen(int m, float e1v, float Ai, float Ci,
    const float* e2f, const float* bfv, const float* dfv, int j)
{
    float s = e1v + e2f[j];
    float pv = (s > 0.f) ? Ai * bfv[j] : Ci * dfv[j];
    return (m > 0) ? pv : 0.f;
}
static __device__ __forceinline__ void psplit_store(char* ph, char* pl, int t,
                                                    float p0, float p1)
{
    bf16 h0, l0, h1, l1;
    fsplit(p0, h0, l0);
    fsplit(p1, h1, l1);
    *(uint32_t*)(ph + 4 * t) = pack2(h0, h1);
    *(uint32_t*)(pl + 4 * t) = pack2(l0, l1);
}

__global__ __launch_bounds__(256, 2) void attn_mma_kernel(
    const float* __restrict__ e1, const int* __restrict__ adj,
    const float* __restrict__ exEh)
{
    extern __shared__ char smem[];
    uint32_t sb = smem_u32(smem);
    float* e2f = (float*)(smem + OFF_E2);
    float* bfv = (float*)(smem + OFF_BF);
    float* dfv = (float*)(smem + OFF_DF);
    float* e1s = (float*)(smem + OFF_E1);
    float* Aes = (float*)(smem + OFF_AE);
    float* Ces = (float*)(smem + OFF_CE);

    int tid = threadIdx.x, lane = tid & 31, wid = tid >> 5;
    int i0 = blockIdx.x * MT;

    for (int j = tid; j < NKC_PAD; j += 256) {
        e2f[j] = g_e2p[j];
        bfv[j] = g_Bf[j];
        dfv[j] = g_Df[j];
    }
    if (tid < MT) {
        int gi = i0 + tid;
        bool v = gi < N_E;
        e1s[tid] = v ? e1[gi] : 0.f;
        Aes[tid] = v ? g_Ae[gi] : 0.f;
        Ces[tid] = v ? g_Ce[gi] : 0.f;
    }
    __syncthreads();

    int r = tid >> 2, q = tid & 3, jl0 = q * 8;
    int gi_r = i0 + r;
    const int* arow = adj + (size_t)(gi_r < N_E ? gi_r : 0) * N_KC;
    float e1v = e1s[r], Ai = Aes[r], Ci = Ces[r];
    float srow = 0.f;

    int wm = wid & 1, wn = wid >> 1;
    float acc[2][8][4];
    #pragma unroll
    for (int mt = 0; mt < 2; mt++)
        #pragma unroll
        for (int nb = 0; nb < 8; nb++)
            #pragma unroll
            for (int k = 0; k < 4; k++) acc[mt][nb][k] = 0.f;

    char* ph = smem + OFF_AHI + r * RSTRIDE + jl0 * 2;
    char* pl = smem + OFF_ALO + r * RSTRIDE + jl0 * 2;

    for (int c = 0; c < NCHUNK; c++) {
        int j0 = c * KC;
        {
            const uint4* sh = (const uint4*)(g_kcWhT_hi + ((size_t)c * 256 + tid) * KC);
            const uint4* sl = (const uint4*)(g_kcWhT_lo + ((size_t)c * 256 + tid) * KC);
            char* dh = smem + OFF_BHI + tid * RSTRIDE;
            char* dl = smem + OFF_BLO + tid * RSTRIDE;
            #pragma unroll
            for (int t = 0; t < 4; t++) {
                *(uint4*)(dh + t * 16) = sh[t];
                *(uint4*)(dl + t * 16) = sl[t];
            }
        }
        if (j0 + KC <= N_KC) {
            const int4* ap = (const int4*)(arow + j0 + jl0);
            int4 a0 = ap[0], a1 = ap[1];
            int am[8] = {a0.x, a0.y, a0.z, a0.w, a1.x, a1.y, a1.z, a1.w};
            #pragma unroll
            for (int t = 0; t < 4; t++) {
                int j = j0 + jl0 + 2 * t;
                float p0 = pgen(am[2 * t],     e1v, Ai, Ci, e2f, bfv, dfv, j);
                float p1 = pgen(am[2 * t + 1], e1v, Ai, Ci, e2f, bfv, dfv, j + 1);
                srow += p0 + p1;
                psplit_store(ph, pl, t, p0, p1);
            }
        } else {
            #pragma unroll
            for (int t = 0; t < 4; t++) {
                int j = j0 + jl0 + 2 * t;
                int m0 = (j     < N_KC) ? arow[j]     : 0;
                int m1 = (j + 1 < N_KC) ? arow[j + 1] : 0;
                float p0 = pgen(m0, e1v, Ai, Ci, e2f, bfv, dfv, (j     < N_KC) ? j     : 0);
                float p1 = pgen(m1, e1v, Ai, Ci, e2f, bfv, dfv, (j + 1 < N_KC) ? j + 1 : 0);
                srow += p0 + p1;
                psplit_store(ph, pl, t, p0, p1);
            }
        }
        __syncthreads();

        #pragma unroll
        for (int ks = 0; ks < 2; ks++) {
            uint32_t ahi[2][4], alo[2][4], bfrag[8][2];
            int arowi = lane & 15;
            int akoff = (ks * 16 + ((lane >> 4) & 1) * 8) * 2;
            #pragma unroll
            for (int mt = 0; mt < 2; mt++) {
                uint32_t ad = sb + OFF_AHI + (wm * 32 + mt * 16 + arowi) * RSTRIDE + akoff;
                LDSM_X4(ahi[mt][0], ahi[mt][1], ahi[mt][2], ahi[mt][3], ad);
                ad += (OFF_ALO - OFF_AHI);
                LDSM_X4(alo[mt][0], alo[mt][1], alo[mt][2], alo[mt][3], ad);
            }
            int bnrow = (lane & 7) + ((lane >> 4) << 3);
            int bkoff = (ks * 16 + ((lane >> 3) & 1) * 8) * 2;
            #pragma unroll
            for (int nq = 0; nq < 4; nq++) {
                uint32_t bd = sb + OFF_BHI + (wn * 64 + nq * 16 + bnrow) * RSTRIDE + bkoff;
                LDSM_X4(bfrag[2 * nq][0], bfrag[2 * nq][1],
                        bfrag[2 * nq + 1][0], bfrag[2 * nq + 1][1], bd);
            }
            #pragma unroll
            for (int mt = 0; mt < 2; mt++)
                #pragma unroll
                for (int nb = 0; nb < 8; nb++)
                    mma_bf16(acc[mt][nb], ahi[mt], bfrag[nb]);
            #pragma unroll
            for (int mt = 0; mt < 2; mt++)
                #pragma unroll
                for (int nb = 0; nb < 8; nb++)
                    mma_bf16(acc[mt][nb], alo[mt], bfrag[nb]);
            #pragma unroll
            for (int nq = 0; nq < 4; nq++) {
                uint32_t bd = sb + OFF_BLO + (wn * 64 + nq * 16 + bnrow) * RSTRIDE + bkoff;
                LDSM_X4(bfrag[2 * nq][0], bfrag[2 * nq][1],
                        bfrag[2 * nq + 1][0], bfrag[2 * nq + 1][1], bd);
            }
            #pragma unroll
            for (int mt = 0; mt < 2; mt++)
                #pragma unroll
                for (int nb = 0; nb < 8; nb++)
                    mma_bf16(acc[mt][nb], ahi[mt], bfrag[nb]);
        }
        __syncthreads();
    }

    ((float*)(smem + OFF_RS))[tid] = srow;
    __syncthreads();
    if (tid < MT) {
        const float* r4 = (const float*)(smem + OFF_RS) + tid * 4;
        ((float*)(smem + OFF_RSF))[tid] = (r4[0] + r4[1]) + (r4[2] + r4[3]);
    }
    __syncthreads();
    const float* rsF = (const float*)(smem + OFF_RSF);

    // epilogue: normalize + write feat = [new_kc, new_kc*exEh] as bf16 hi/lo
    #pragma unroll
    for (int mt = 0; mt < 2; mt++) {
        #pragma unroll
        for (int nb = 0; nb < 8; nb++) {
            int row0 = wm * 32 + mt * 16 + (lane >> 2);
            int col  = wn * 64 + nb * 8 + (lane & 3) * 2;
            #pragma unroll
            for (int h = 0; h < 2; h++) {
                int rr = row0 + h * 8;
                int gi = i0 + rr;
                if (gi >= N_E) continue;
                float v0 = acc[mt][nb][2 * h];
                float v1 = acc[mt][nb][2 * h + 1];
                float rs = rsF[rr];
                float nk0, nk1;
                if (rs > 0.f) {
                    float ri = 1.f / rs;
                    nk0 = v0 * ri;
                    nk1 = v1 * ri;
                } else {
                    nk0 = g_colmean[col];
                    nk1 = g_colmean[col + 1];
                }
                float x0 = exEh[(size_t)gi * OUT_F + col];
                float x1 = exEh[(size_t)gi * OUT_F + col + 1];
                float q0 = nk0 * x0, q1 = nk1 * x1;
                size_t fb = (size_t)gi * (2 * OUT_F);
                bf16 h0, l0, h1, l1;
                fsplit(nk0, h0, l0); fsplit(nk1, h1, l1);
                *(uint32_t*)(g_feathi + fb + col) = pack2(h0, h1);
                *(uint32_t*)(g_featlo + fb + col) = pack2(l0, l1);
                fsplit(q0, h0, l0); fsplit(q1, h1, l1);
                *(uint32_t*)(g_feathi + fb + OUT_F + col) = pack2(h0, h1);
                *(uint32_t*)(g_featlo + fb + OUT_F + col) = pack2(l0, l1);
            }
        }
    }
}

// ---------------- launch ----------------
extern "C" void kernel_launch(void* const* d_in, const int* in_sizes, int n_in,
                              void* d_out, int out_size)
{
    const float* ex   = (const float*)d_in[0];
    const float* kc   = (const float*)d_in[1];
    const int*   adj  = (const int*)d_in[2];
    const float* W1   = (const float*)d_in[3];
    const float* E    = (const float*)d_in[4];
    const float* a    = (const float*)d_in[5];
    const float* rd_w = (const float*)d_in[6];
    const float* rd_b = (const float*)d_in[7];
    float* out = (float*)d_out;

    float *kcWh, *exEh, *e1, *e2, *v1, *v2;
    bf16 *exhi, *exlo, *kchi, *kclo, *W1Thi, *W1Tlo, *EThi, *ETlo;
    bf16 *rdwhi, *rdwlo, *feathi, *featlo;
    cudaGetSymbolAddress((void**)&kcWh, g_kcWh);
    cudaGetSymbolAddress((void**)&exEh, g_exEh);
    cudaGetSymbolAddress((void**)&e1, g_e1);
    cudaGetSymbolAddress((void**)&e2, g_e2);
    cudaGetSymbolAddress((void**)&v1, g_v1);
    cudaGetSymbolAddress((void**)&v2, g_v2);
    cudaGetSymbolAddress((void**)&exhi, g_exhi);
    cudaGetSymbolAddress((void**)&exlo, g_exlo);
    cudaGetSymbolAddress((void**)&kchi, g_kchi);
    cudaGetSymbolAddress((void**)&kclo, g_kclo);
    cudaGetSymbolAddress((void**)&W1Thi, g_W1Thi);
    cudaGetSymbolAddress((void**)&W1Tlo, g_W1Tlo);
    cudaGetSymbolAddress((void**)&EThi, g_EThi);
    cudaGetSymbolAddress((void**)&ETlo, g_ETlo);
    cudaGetSymbolAddress((void**)&rdwhi, g_rdwhi);
    cudaGetSymbolAddress((void**)&rdwlo, g_rdwlo);
    cudaGetSymbolAddress((void**)&feathi, g_feathi);
    cudaGetSymbolAddress((void**)&featlo, g_featlo);

    cudaFuncSetAttribute(attn_mma_kernel,
                         cudaFuncAttributeMaxDynamicSharedMemorySize, SMEM_ATTN);

    // 1. v1 = W1@a1, v2 = W1@a2
    prep_kernel<<<1, 256>>>(W1, a);

    // 2. operand splits
    split_kernel<<<(N_E * IN_F / 4 + 255) / 256, 256>>>(ex, exhi, exlo, N_E * IN_F);
    split_kernel<<<(N_KC * IN_F / 4 + 255) / 256, 256>>>(kc, kchi, kclo, N_KC * IN_F);
    split_kernel<<<(OUT_F * 2 * OUT_F / 4 + 255) / 256, 256>>>(rd_w, rdwhi, rdwlo, OUT_F * 2 * OUT_F);
    tsplit_kernel<<<dim3(IN_F / 32, OUT_F / 32), 256>>>(W1, W1Thi, W1Tlo, IN_F, OUT_F);
    tsplit_kernel<<<dim3(IN_F / 32, OUT_F / 32), 256>>>(E, EThi, ETlo, IN_F, OUT_F);

    // 3. kc_Wh = kc @ W1   [2000,256]
    hgemm_kernel<<<dim3(OUT_F / 128, (N_KC + 127) / 128), 256>>>(
        kchi, kclo, W1Thi, W1Tlo, kcWh, N_KC, OUT_F, IN_F, nullptr, 0);

    // 4. e1 = ex @ v1, e2 = kc @ v2, exp tables
    rowdot_kernel<<<(N_E * 32 + 255) / 256, 256>>>(ex, v1, e1, N_E);
    rowdot_kernel<<<(N_KC * 32 + 255) / 256, 256>>>(kc, v2, e2, N_KC);
    expprep_kernel<<<(N_E + 255) / 256, 256>>>();

    // 5. ex_Eh = ex @ E   [10000,256]
    hgemm_kernel<<<dim3(OUT_F / 128, (N_E + 127) / 128), 256>>>(
        exhi, exlo, EThi, ETlo, exEh, N_E, OUT_F, IN_F, nullptr, 0);

    // 6. kcWh -> chunk-blocked transposed bf16 hi/lo + column mean
    conv_kernel<<<dim3(NKC_PAD / 32, OUT_F / 32), 256>>>(kcWh);
    colmean_kernel<<<1, OUT_F>>>(kcWh);

    // 7. attention -> feat hi/lo [10000, 512]
    attn_mma_kernel<<<(N_E + MT - 1) / MT, 256, SMEM_ATTN>>>(e1, adj, exEh);

    // 8. out = elu(feat @ rd_w^T + rd_b)   [10000,256]
    hgemm_kernel<<<dim3(OUT_F / 128, (N_E + 127) / 128), 256>>>(
        feathi, featlo, rdwhi, rdwlo, out, N_E, OUT_F, 2 * OUT_F, rd_b, 1);
}

// round 7
// speedup vs baseline: 1.8709x; 1.1057x over previous
#include <cuda_runtime.h>
#include <cuda_bf16.h>
#include <math.h>
#include <stdint.h>

#define IN_F   256
#define OUT_F  256
#define N_E    10000
#define N_KC   2000
#define ALPHA  0.2f

#define MT      64            // rows per attention block tile
#define KC      32            // j per K-chunk
#define NKC_PAD 2048
#define NCHUNK_RUN 63         // chunk 63 (j 2016..2047) is all padding -> skipped
#define RSTRIDE 80            // bytes per smem tile row (64B data + 16B pad)

typedef __nv_bfloat16 bf16;

// ---------------- scratch (static __device__, no allocation) ----------------
__device__ float g_kcWh[N_KC * OUT_F];
__device__ float g_exEh[N_E * OUT_F];
__device__ float g_e1[N_E];
__device__ float g_v1[IN_F];
__device__ float g_v2[IN_F];
// chunk-blocked transposed kcWh for attention B: ((chunk*256 + n)*KC + j%KC)
__device__ bf16 g_kcWhT_hi[OUT_F * NKC_PAD];
__device__ bf16 g_kcWhT_lo[OUT_F * NKC_PAD];
__device__ float g_colmean[OUT_F];
__device__ float g_mkcp[8][IN_F];   // partial column sums of kc
// separable-exp tables
__device__ float g_Ae[N_E];
__device__ float g_Ce[N_E];
__device__ float g_Bf[NKC_PAD];
__device__ float g_Df[NKC_PAD];
__device__ float g_e2p[NKC_PAD];
// hi/lo split operands for mma GEMMs
__device__ bf16 g_exhi[N_E * IN_F];
__device__ bf16 g_exlo[N_E * IN_F];
__device__ bf16 g_kchi[N_KC * IN_F];
__device__ bf16 g_kclo[N_KC * IN_F];
__device__ bf16 g_W1Thi[OUT_F * IN_F];   // [n][k]
__device__ bf16 g_W1Tlo[OUT_F * IN_F];
__device__ bf16 g_EThi[OUT_F * IN_F];    // [n][k]
__device__ bf16 g_ETlo[OUT_F * IN_F];
__device__ bf16 g_rdwhi[OUT_F * 2 * OUT_F]; // rd_w is [n=256][k=512]
__device__ bf16 g_rdwlo[OUT_F * 2 * OUT_F];
__device__ bf16 g_feathi[N_E * 2 * OUT_F];
__device__ bf16 g_featlo[N_E * 2 * OUT_F];

// ---------------- helpers ----------------
static __device__ __forceinline__ uint32_t smem_u32(const void* p) {
    uint32_t a;
    asm("{ .reg .u64 t; cvta.to.shared.u64 t, %1; cvt.u32.u64 %0, t; }" : "=r"(a) : "l"(p));
    return a;
}
#define LDSM_X4(R0,R1,R2,R3,ADDR) \
    asm volatile("ldmatrix.sync.aligned.m8n8.x4.shared.b16 {%0,%1,%2,%3}, [%4];" \
                 : "=r"(R0),"=r"(R1),"=r"(R2),"=r"(R3) : "r"(ADDR))

static __device__ __forceinline__ void mma_bf16(float* c, const uint32_t* a, const uint32_t* b) {
    asm volatile(
        "mma.sync.aligned.m16n8k16.row.col.f32.bf16.bf16.f32 "
        "{%0,%1,%2,%3}, {%4,%5,%6,%7}, {%8,%9}, {%0,%1,%2,%3};"
        : "+f"(c[0]), "+f"(c[1]), "+f"(c[2]), "+f"(c[3])
        : "r"(a[0]), "r"(a[1]), "r"(a[2]), "r"(a[3]), "r"(b[0]), "r"(b[1]));
}
static __device__ __forceinline__ void fsplit(float v, bf16& h, bf16& l) {
    h = __float2bfloat16(v);
    l = __float2bfloat16(v - __bfloat162float(h));
}
static __device__ __forceinline__ uint32_t pack2(bf16 a, bf16 b) {
    __nv_bfloat162 t = __halves2bfloat162(a, b);
    return *(uint32_t*)&t;
}
static __device__ __forceinline__ void split4_store(const float4 v, bf16* hi, bf16* lo) {
    bf16 h0, l0, h1, l1, h2, l2, h3, l3;
    fsplit(v.x, h0, l0); fsplit(v.y, h1, l1);
    fsplit(v.z, h2, l2); fsplit(v.w, h3, l3);
    *(uint32_t*)(hi)     = pack2(h0, h1);
    *(uint32_t*)(hi + 2) = pack2(h2, h3);
    *(uint32_t*)(lo)     = pack2(l0, l1);
    *(uint32_t*)(lo + 2) = pack2(l2, l3);
}

// ---------------- mega kernel: prep + all splits + kc col-sum partials ----------------
// segments: [0,1) prep | [1,2501) split ex | [2501,3001) split kc |
//           [3001,3129) split rdw | [3129,3193) tsplit W1 | [3193,3257) tsplit E |
//           [3257,3265) mkc partials
#define MB_PREP 0
#define MB_EX   1
#define MB_KC   2501
#define MB_RDW  3001
#define MB_TW1  3129
#define MB_TE   3193
#define MB_MKC  3257
#define MB_TOT  3265
__global__ void mega_kernel(const float* __restrict__ ex, const float* __restrict__ kc,
                            const float* __restrict__ rdw, const float* __restrict__ W1,
                            const float* __restrict__ E, const float* __restrict__ a)
{
    int b = blockIdx.x, tid = threadIdx.x;
    if (b < MB_EX) {
        // prep: v1 = W1@a1, v2 = W1@a2
        int k = tid;
        float s1 = 0.f, s2 = 0.f;
        #pragma unroll 8
        for (int j = 0; j < OUT_F; j++) {
            float w = W1[k * OUT_F + j];
            s1 += w * a[j];
            s2 += w * a[OUT_F + j];
        }
        g_v1[k] = s1;
        g_v2[k] = s2;
    } else if (b < MB_KC) {
        size_t i = ((size_t)(b - MB_EX) * 256 + tid) * 4;
        split4_store(*(const float4*)(ex + i), g_exhi + i, g_exlo + i);
    } else if (b < MB_RDW) {
        size_t i = ((size_t)(b - MB_KC) * 256 + tid) * 4;
        split4_store(*(const float4*)(kc + i), g_kchi + i, g_kclo + i);
    } else if (b < MB_TW1) {
        size_t i = ((size_t)(b - MB_RDW) * 256 + tid) * 4;
        split4_store(*(const float4*)(rdw + i), g_rdwhi + i, g_rdwlo + i);
    } else if (b < MB_MKC) {
        // transpose + split: src [K=256][N=256] -> [N][K]
        bool isW1 = b < MB_TE;
        int bb = b - (isW1 ? MB_TW1 : MB_TE);
        const float* src = isW1 ? W1 : E;
        bf16* hi = isW1 ? g_W1Thi : g_EThi;
        bf16* lo = isW1 ? g_W1Tlo : g_ETlo;
        __shared__ float t[32][33];
        int kb = (bb & 7) * 32, nb = (bb >> 3) * 32;
        int tx = tid & 31, ty = tid >> 5;
        #pragma unroll
        for (int rr = 0; rr < 32; rr += 8)
            t[ty + rr][tx] = src[(size_t)(kb + ty + rr) * OUT_F + nb + tx];
        __syncthreads();
        #pragma unroll
        for (int rr = 0; rr < 32; rr += 8) {
            int n = nb + ty + rr;
            bf16 h, l;
            fsplit(t[tx][ty + rr], h, l);
            hi[(size_t)n * IN_F + kb + tx] = h;
            lo[(size_t)n * IN_F + kb + tx] = l;
        }
    } else {
        // kc column-sum partials: block p sums rows [p*250, (p+1)*250)
        int p = b - MB_MKC;
        float s = 0.f;
        for (int j = p * 250; j < (p + 1) * 250; j++)
            s += kc[(size_t)j * IN_F + tid];
        g_mkcp[p][tid] = s;
    }
}

// ---------------- rowdot_both: e1 rows + e2 rows (with fused exp) + colmean ----------------
// blocks [0,1250): e1; [1250,1506): e2/pad; [1506]: colmean = mean(kc) @ W1
#define RB_E2  1250
#define RB_CM  1506
#define RB_TOT 1507
__global__ void rowdot_both_kernel(const float* __restrict__ ex, const float* __restrict__ kc,
                                   const float* __restrict__ W1)
{
    int b = blockIdx.x, tid = threadIdx.x;
    int lane = tid & 31, warp = tid >> 5;
    if (b < RB_E2) {
        int i = b * 8 + warp;
        if (i >= N_E) return;
        const float* row = ex + (size_t)i * IN_F;
        float s = 0.f;
        #pragma unroll
        for (int k = lane; k < IN_F; k += 32) s += row[k] * g_v1[k];
        #pragma unroll
        for (int o = 16; o; o >>= 1) s += __shfl_xor_sync(0xFFFFFFFFu, s, o);
        if (lane == 0) {
            g_e1[i] = s;
            g_Ae[i] = __expf(s);
            g_Ce[i] = __expf(ALPHA * s);
        }
    } else if (b < RB_CM) {
        int j = (b - RB_E2) * 8 + warp;
        if (j >= NKC_PAD) return;
        float s = 0.f;
        if (j < N_KC) {
            const float* row = kc + (size_t)j * IN_F;
            #pragma unroll
            for (int k = lane; k < IN_F; k += 32) s += row[k] * g_v2[k];
            #pragma unroll
            for (int o = 16; o; o >>= 1) s += __shfl_xor_sync(0xFFFFFFFFu, s, o);
            if (lane == 0) {
                g_e2p[j] = s;
                g_Bf[j] = __expf(s);
                g_Df[j] = __expf(ALPHA * s);
            }
        } else if (lane == 0) {
            g_e2p[j] = 0.f;
            g_Bf[j] = 0.f;
            g_Df[j] = 0.f;
        }
    } else {
        // colmean[n] = (1/N_KC) * sum_k S[k] * W1[k][n], S = col sums of kc
        __shared__ float S[IN_F];
        float s = 0.f;
        #pragma unroll
        for (int p = 0; p < 8; p++) s += g_mkcp[p][tid];
        S[tid] = s;
        __syncthreads();
        float c = 0.f;
        #pragma unroll 8
        for (int k = 0; k < IN_F; k++)
            c += S[k] * W1[(size_t)k * OUT_F + tid];
        g_colmean[tid] = c * (1.0f / N_KC);
    }
}

// ---------------- transpose+convert kcWh -> chunk-blocked bf16 hi/lo ----------------
__global__ void conv_kernel(const float* __restrict__ kcWh)
{
    __shared__ float t[32][33];
    int jb = blockIdx.x * 32, nb = blockIdx.y * 32;
    int tx = threadIdx.x & 31, ty = threadIdx.x >> 5;
    #pragma unroll
    for (int rr = 0; rr < 32; rr += 8) {
        int j = jb + ty + rr, n = nb + tx;
        t[ty + rr][tx] = (j < N_KC) ? kcWh[(size_t)j * OUT_F + n] : 0.f;
    }
    __syncthreads();
    #pragma unroll
    for (int rr = 0; rr < 32; rr += 8) {
        int n = nb + ty + rr;
        bf16 h, l;
        fsplit(t[tx][ty + rr], h, l);
        size_t di = ((size_t)(jb >> 5) * 256 + n) * KC + tx;
        g_kcWhT_hi[di] = h;
        g_kcWhT_lo[di] = l;
    }
}

// ---------------- bf16 hi/lo tensor-core GEMM ----------------
// C[M][N] = A @ B^T. Block 128x128, 8 warps (4Mx2N), warp tile 32x64.
#define HOF_AH 0
#define HOF_AL 10240
#define HOF_BH 20480
#define HOF_BL 30720
__global__ __launch_bounds__(256, 2) void hgemm_kernel(
    const bf16* __restrict__ Ahi, const bf16* __restrict__ Alo,
    const bf16* __restrict__ Bhi, const bf16* __restrict__ Blo,
    float* __restrict__ C, int M, int N, int K,
    const float* __restrict__ bias, int epi)
{
    __shared__ char smem[40960];
    uint32_t sb = smem_u32(smem);
    int tid = threadIdx.x, lane = tid & 31, wid = tid >> 5;
    int bm = blockIdx.y * 128, bn = blockIdx.x * 128;
    int wm = wid >> 1, wn = wid & 1;

    float acc[2][8][4];
    #pragma unroll
    for (int mt = 0; mt < 2; mt++)
        #pragma unroll
        for (int nb = 0; nb < 8; nb++)
            #pragma unroll
            for (int k = 0; k < 4; k++) acc[mt][nb][k] = 0.f;

    int crow = tid >> 1, chalf = tid & 1;
    bool arow_ok = (bm + crow) < M;
    const uint4 zero4 = make_uint4(0, 0, 0, 0);

    for (int k0 = 0; k0 < K; k0 += 32) {
        {
            char* dh = smem + HOF_AH + crow * RSTRIDE + chalf * 32;
            char* dl = smem + HOF_AL + crow * RSTRIDE + chalf * 32;
            if (arow_ok) {
                const uint4* sh = (const uint4*)(Ahi + (size_t)(bm + crow) * K + k0 + chalf * 16);
                const uint4* sl = (const uint4*)(Alo + (size_t)(bm + crow) * K + k0 + chalf * 16);
                ((uint4*)dh)[0] = sh[0]; ((uint4*)dh)[1] = sh[1];
                ((uint4*)dl)[0] = sl[0]; ((uint4*)dl)[1] = sl[1];
            } else {
                ((uint4*)dh)[0] = zero4; ((uint4*)dh)[1] = zero4;
                ((uint4*)dl)[0] = zero4; ((uint4*)dl)[1] = zero4;
            }
        }
        {
            const uint4* sh = (const uint4*)(Bhi + (size_t)(bn + crow) * K + k0 + chalf * 16);
            const uint4* sl = (const uint4*)(Blo + (size_t)(bn + crow) * K + k0 + chalf * 16);
            char* dh = smem + HOF_BH + crow * RSTRIDE + chalf * 32;
            char* dl = smem + HOF_BL + crow * RSTRIDE + chalf * 32;
            ((uint4*)dh)[0] = sh[0]; ((uint4*)dh)[1] = sh[1];
            ((uint4*)dl)[0] = sl[0]; ((uint4*)dl)[1] = sl[1];
        }
        __syncthreads();

        #pragma unroll
        for (int ks = 0; ks < 2; ks++) {
            uint32_t ahi[2][4], alo[2][4], bfrag[8][2];
            int arowi = lane & 15;
            int akoff = (ks * 16 + ((lane >> 4) & 1) * 8) * 2;
            #pragma unroll
            for (int mt = 0; mt < 2; mt++) {
                uint32_t ad = sb + HOF_AH + (wm * 32 + mt * 16 + arowi) * RSTRIDE + akoff;
                LDSM_X4(ahi[mt][0], ahi[mt][1], ahi[mt][2], ahi[mt][3], ad);
                ad += (HOF_AL - HOF_AH);
                LDSM_X4(alo[mt][0], alo[mt][1], alo[mt][2], alo[mt][3], ad);
            }
            int bnrow = (lane & 7) + ((lane >> 4) << 3);
            int bkoff = (ks * 16 + ((lane >> 3) & 1) * 8) * 2;
            #pragma unroll
            for (int nq = 0; nq < 4; nq++) {
                uint32_t bd = sb + HOF_BH + (wn * 64 + nq * 16 + bnrow) * RSTRIDE + bkoff;
                LDSM_X4(bfrag[2 * nq][0], bfrag[2 * nq][1],
                        bfrag[2 * nq + 1][0], bfrag[2 * nq + 1][1], bd);
            }
            #pragma unroll
            for (int mt = 0; mt < 2; mt++)
                #pragma unroll
                for (int nb = 0; nb < 8; nb++)
                    mma_bf16(acc[mt][nb], ahi[mt], bfrag[nb]);
            #pragma unroll
            for (int mt = 0; mt < 2; mt++)
                #pragma unroll
                for (int nb = 0; nb < 8; nb++)
                    mma_bf16(acc[mt][nb], alo[mt], bfrag[nb]);
            #pragma unroll
            for (int nq = 0; nq < 4; nq++) {
                uint32_t bd = sb + HOF_BL + (wn * 64 + nq * 16 + bnrow) * RSTRIDE + bkoff;
                LDSM_X4(bfrag[2 * nq][0], bfrag[2 * nq][1],
                        bfrag[2 * nq + 1][0], bfrag[2 * nq + 1][1], bd);
            }
            #pragma unroll
            for (int mt = 0; mt < 2; mt++)
                #pragma unroll
                for (int nb = 0; nb < 8; nb++)
                    mma_bf16(acc[mt][nb], ahi[mt], bfrag[nb]);
        }
        __syncthreads();
    }

    #pragma unroll
    for (int mt = 0; mt < 2; mt++) {
        #pragma unroll
        for (int nb = 0; nb < 8; nb++) {
            int row0 = wm * 32 + mt * 16 + (lane >> 2);
            int col = bn + wn * 64 + nb * 8 + (lane & 3) * 2;
            #pragma unroll
            for (int h = 0; h < 2; h++) {
                int r = bm + row0 + h * 8;
                if (r >= M) continue;
                float v0 = acc[mt][nb][2 * h];
                float v1 = acc[mt][nb][2 * h + 1];
                if (epi == 1) {
                    v0 += bias[col];
                    v1 += bias[col + 1];
                    v0 = v0 > 0.f ? v0 : expm1f(v0);
                    v1 = v1 > 0.f ? v1 : expm1f(v1);
                }
                C[(size_t)r * N + col]     = v0;
                C[(size_t)r * N + col + 1] = v1;
            }
        }
    }
}

// ---------------- attention: P-gen + warp-level bf16 hi/lo mma.sync ----------------
#define OFF_BHI 0
#define OFF_BLO 20480
#define OFF_AHI 40960
#define OFF_ALO 46080
#define OFF_E2  51200
#define OFF_BF  59392
#define OFF_DF  67584
#define OFF_E1  75776
#define OFF_AE  76032
#define OFF_CE  76288
#define OFF_RS  76544
#define OFF_RSF 77568
#define SMEM_ATTN 77824

static __device__ __forceinline__ float pgen(int m, float e1v, float Ai, float Ci,
    const float* e2f, const float* bfv, const float* dfv, int j)
{
    float s = e1v + e2f[j];
    float pv = (s > 0.f) ? Ai * bfv[j] : Ci * dfv[j];
    return (m > 0) ? pv : 0.f;
}
static __device__ __forceinline__ void psplit_store(char* ph, char* pl, int t,
                                                    float p0, float p1)
{
    bf16 h0, l0, h1, l1;
    fsplit(p0, h0, l0);
    fsplit(p1, h1, l1);
    *(uint32_t*)(ph + 4 * t) = pack2(h0, h1);
    *(uint32_t*)(pl + 4 * t) = pack2(l0, l1);
}

__global__ __launch_bounds__(256, 2) void attn_mma_kernel(
    const float* __restrict__ e1, const int* __restrict__ adj,
    const float* __restrict__ exEh)
{
    extern __shared__ char smem[];
    uint32_t sb = smem_u32(smem);
    float* e2f = (float*)(smem + OFF_E2);
    float* bfv = (float*)(smem + OFF_BF);
    float* dfv = (float*)(smem + OFF_DF);
    float* e1s = (float*)(smem + OFF_E1);
    float* Aes = (float*)(smem + OFF_AE);
    float* Ces = (float*)(smem + OFF_CE);

    int tid = threadIdx.x, lane = tid & 31, wid = tid >> 5;
    int i0 = blockIdx.x * MT;

    for (int j = tid; j < NKC_PAD; j += 256) {
        e2f[j] = g_e2p[j];
        bfv[j] = g_Bf[j];
        dfv[j] = g_Df[j];
    }
    if (tid < MT) {
        int gi = i0 + tid;
        bool v = gi < N_E;
        e1s[tid] = v ? e1[gi] : 0.f;
        Aes[tid] = v ? g_Ae[gi] : 0.f;
        Ces[tid] = v ? g_Ce[gi] : 0.f;
    }
    __syncthreads();

    int r = tid >> 2, q = tid & 3, jl0 = q * 8;
    int gi_r = i0 + r;
    const int* arow = adj + (size_t)(gi_r < N_E ? gi_r : 0) * N_KC;
    float e1v = e1s[r], Ai = Aes[r], Ci = Ces[r];
    float srow = 0.f;

    int wm = wid & 1, wn = wid >> 1;
    float acc[2][8][4];
    #pragma unroll
    for (int mt = 0; mt < 2; mt++)
        #pragma unroll
        for (int nb = 0; nb < 8; nb++)
            #pragma unroll
            for (int k = 0; k < 4; k++) acc[mt][nb][k] = 0.f;

    char* ph = smem + OFF_AHI + r * RSTRIDE + jl0 * 2;
    char* pl = smem + OFF_ALO + r * RSTRIDE + jl0 * 2;

    for (int c = 0; c < NCHUNK_RUN; c++) {
        int j0 = c * KC;
        {
            const uint4* sh = (const uint4*)(g_kcWhT_hi + ((size_t)c * 256 + tid) * KC);
            const uint4* sl = (const uint4*)(g_kcWhT_lo + ((size_t)c * 256 + tid) * KC);
            char* dh = smem + OFF_BHI + tid * RSTRIDE;
            char* dl = smem + OFF_BLO + tid * RSTRIDE;
            #pragma unroll
            for (int t = 0; t < 4; t++) {
                *(uint4*)(dh + t * 16) = sh[t];
                *(uint4*)(dl + t * 16) = sl[t];
            }
        }
        if (j0 + KC <= N_KC) {
            const int4* ap = (const int4*)(arow + j0 + jl0);
            int4 a0 = ap[0], a1 = ap[1];
            int am[8] = {a0.x, a0.y, a0.z, a0.w, a1.x, a1.y, a1.z, a1.w};
            #pragma unroll
            for (int t = 0; t < 4; t++) {
                int j = j0 + jl0 + 2 * t;
                float p0 = pgen(am[2 * t],     e1v, Ai, Ci, e2f, bfv, dfv, j);
                float p1 = pgen(am[2 * t + 1], e1v, Ai, Ci, e2f, bfv, dfv, j + 1);
                srow += p0 + p1;
                psplit_store(ph, pl, t, p0, p1);
            }
        } else {
            #pragma unroll
            for (int t = 0; t < 4; t++) {
                int j = j0 + jl0 + 2 * t;
                int m0 = (j     < N_KC) ? arow[j]     : 0;
                int m1 = (j + 1 < N_KC) ? arow[j + 1] : 0;
                float p0 = pgen(m0, e1v, Ai, Ci, e2f, bfv, dfv, (j     < N_KC) ? j     : 0);
                float p1 = pgen(m1, e1v, Ai, Ci, e2f, bfv, dfv, (j + 1 < N_KC) ? j + 1 : 0);
                srow += p0 + p1;
                psplit_store(ph, pl, t, p0, p1);
            }
        }
        __syncthreads();

        #pragma unroll
        for (int ks = 0; ks < 2; ks++) {
            uint32_t ahi[2][4], alo[2][4], bfrag[8][2];
            int arowi = lane & 15;
            int akoff = (ks * 16 + ((lane >> 4) & 1) * 8) * 2;
            #pragma unroll
            for (int mt = 0; mt < 2; mt++) {
                uint32_t ad = sb + OFF_AHI + (wm * 32 + mt * 16 + arowi) * RSTRIDE + akoff;
                LDSM_X4(ahi[mt][0], ahi[mt][1], ahi[mt][2], ahi[mt][3], ad);
                ad += (OFF_ALO - OFF_AHI);
                LDSM_X4(alo[mt][0], alo[mt][1], alo[mt][2], alo[mt][3], ad);
            }
            int bnrow = (lane & 7) + ((lane >> 4) << 3);
            int bkoff = (ks * 16 + ((lane >> 3) & 1) * 8) * 2;
            #pragma unroll
            for (int nq = 0; nq < 4; nq++) {
                uint32_t bd = sb + OFF_BHI + (wn * 64 + nq * 16 + bnrow) * RSTRIDE + bkoff;
                LDSM_X4(bfrag[2 * nq][0], bfrag[2 * nq][1],
                        bfrag[2 * nq + 1][0], bfrag[2 * nq + 1][1], bd);
            }
            #pragma unroll
            for (int mt = 0; mt < 2; mt++)
                #pragma unroll
                for (int nb = 0; nb < 8; nb++)
                    mma_bf16(acc[mt][nb], ahi[mt], bfrag[nb]);
            #pragma unroll
            for (int mt = 0; mt < 2; mt++)
                #pragma unroll
                for (int nb = 0; nb < 8; nb++)
                    mma_bf16(acc[mt][nb], alo[mt], bfrag[nb]);
            #pragma unroll
            for (int nq = 0; nq < 4; nq++) {
                uint32_t bd = sb + OFF_BLO + (wn * 64 + nq * 16 + bnrow) * RSTRIDE + bkoff;
                LDSM_X4(bfrag[2 * nq][0], bfrag[2 * nq][1],
                        bfrag[2 * nq + 1][0], bfrag[2 * nq + 1][1], bd);
            }
            #pragma unroll
            for (int mt = 0; mt < 2; mt++)
                #pragma unroll
                for (int nb = 0; nb < 8; nb++)
                    mma_bf16(acc[mt][nb], ahi[mt], bfrag[nb]);
        }
        __syncthreads();
    }

    ((float*)(smem + OFF_RS))[tid] = srow;
    __syncthreads();
    if (tid < MT) {
        const float* r4 = (const float*)(smem + OFF_RS) + tid * 4;
        ((float*)(smem + OFF_RSF))[tid] = (r4[0] + r4[1]) + (r4[2] + r4[3]);
    }
    __syncthreads();
    const float* rsF = (const float*)(smem + OFF_RSF);

    #pragma unroll
    for (int mt = 0; mt < 2; mt++) {
        #pragma unroll
        for (int nb = 0; nb < 8; nb++) {
            int row0 = wm * 32 + mt * 16 + (lane >> 2);
            int col  = wn * 64 + nb * 8 + (lane & 3) * 2;
            #pragma unroll
            for (int h = 0; h < 2; h++) {
                int rr = row0 + h * 8;
                int gi = i0 + rr;
                if (gi >= N_E) continue;
                float v0 = acc[mt][nb][2 * h];
                float v1 = acc[mt][nb][2 * h + 1];
                float rs = rsF[rr];
                float nk0, nk1;
                if (rs > 0.f) {
                    float ri = 1.f / rs;
                    nk0 = v0 * ri;
                    nk1 = v1 * ri;
                } else {
                    nk0 = g_colmean[col];
                    nk1 = g_colmean[col + 1];
                }
                float x0 = exEh[(size_t)gi * OUT_F + col];
                float x1 = exEh[(size_t)gi * OUT_F + col + 1];
                float q0 = nk0 * x0, q1 = nk1 * x1;
                size_t fb = (size_t)gi * (2 * OUT_F);
                bf16 h0, l0, h1, l1;
                fsplit(nk0, h0, l0); fsplit(nk1, h1, l1);
                *(uint32_t*)(g_feathi + fb + col) = pack2(h0, h1);
                *(uint32_t*)(g_featlo + fb + col) = pack2(l0, l1);
                fsplit(q0, h0, l0); fsplit(q1, h1, l1);
                *(uint32_t*)(g_feathi + fb + OUT_F + col) = pack2(h0, h1);
                *(uint32_t*)(g_featlo + fb + OUT_F + col) = pack2(l0, l1);
            }
        }
    }
}

// ---------------- launch ----------------
extern "C" void kernel_launch(void* const* d_in, const int* in_sizes, int n_in,
                              void* d_out, int out_size)
{
    const float* ex   = (const float*)d_in[0];
    const float* kc   = (const float*)d_in[1];
    const int*   adj  = (const int*)d_in[2];
    const float* W1   = (const float*)d_in[3];
    const float* E    = (const float*)d_in[4];
    const float* a    = (const float*)d_in[5];
    const float* rd_w = (const float*)d_in[6];
    const float* rd_b = (const float*)d_in[7];
    float* out = (float*)d_out;

    float *kcWh, *exEh, *e1;
    bf16 *exhi, *exlo, *kchi, *kclo, *W1Thi, *W1Tlo, *EThi, *ETlo;
    bf16 *rdwhi, *rdwlo, *feathi, *featlo;
    cudaGetSymbolAddress((void**)&kcWh, g_kcWh);
    cudaGetSymbolAddress((void**)&exEh, g_exEh);
    cudaGetSymbolAddress((void**)&e1, g_e1);
    cudaGetSymbolAddress((void**)&exhi, g_exhi);
    cudaGetSymbolAddress((void**)&exlo, g_exlo);
    cudaGetSymbolAddress((void**)&kchi, g_kchi);
    cudaGetSymbolAddress((void**)&kclo, g_kclo);
    cudaGetSymbolAddress((void**)&W1Thi, g_W1Thi);
    cudaGetSymbolAddress((void**)&W1Tlo, g_W1Tlo);
    cudaGetSymbolAddress((void**)&EThi, g_EThi);
    cudaGetSymbolAddress((void**)&ETlo, g_ETlo);
    cudaGetSymbolAddress((void**)&rdwhi, g_rdwhi);
    cudaGetSymbolAddress((void**)&rdwlo, g_rdwlo);
    cudaGetSymbolAddress((void**)&feathi, g_feathi);
    cudaGetSymbolAddress((void**)&featlo, g_featlo);

    cudaFuncSetAttribute(attn_mma_kernel,
                         cudaFuncAttributeMaxDynamicSharedMemorySize, SMEM_ATTN);

    // 0. prep + splits + kc colsum partials
    mega_kernel<<<MB_TOT, 256>>>(ex, kc, rd_w, W1, E, a);

    // 1. kc_Wh = kc @ W1   [2000,256]
    hgemm_kernel<<<dim3(OUT_F / 128, (N_KC + 127) / 128), 256>>>(
        kchi, kclo, W1Thi, W1Tlo, kcWh, N_KC, OUT_F, IN_F, nullptr, 0);

    // 2. e1/e2 rowdots + exp tables + colmean
    rowdot_both_kernel<<<RB_TOT, 256>>>(ex, kc, W1);

    // 3. kcWh -> chunk-blocked transposed bf16 hi/lo
    conv_kernel<<<dim3(NKC_PAD / 32, OUT_F / 32), 256>>>(kcWh);

    // 4. ex_Eh = ex @ E   [10000,256]
    hgemm_kernel<<<dim3(OUT_F / 128, (N_E + 127) / 128), 256>>>(
        exhi, exlo, EThi, ETlo, exEh, N_E, OUT_F, IN_F, nullptr, 0);

    // 5. attention -> feat hi/lo [10000, 512]   (profiled launch)
    attn_mma_kernel<<<(N_E + MT - 1) / MT, 256, SMEM_ATTN>>>(e1, adj, exEh);

    // 6. out = elu(feat @ rd_w^T + rd_b)   [10000,256]
    hgemm_kernel<<<dim3(OUT_F / 128, (N_E + 127) / 128), 256>>>(
        feathi, featlo, rdwhi, rdwlo, out, N_E, OUT_F, 2 * OUT_F, rd_b, 1);
}